// round 8
// baseline (speedup 1.0000x reference)
#include <cuda_runtime.h>
#include <cuda_bf16.h>
#include <math.h>
#include <stdint.h>

#define B_ 2
#define S_ 2048
#define D_ 1024
#define H_ 16
#define DH_ 64
#define NTOK 4096
#define OUT_ELEMS ((size_t)NTOK * D_)

// ---------------- pre-split bf16 hi/lo scratch -------------------------------
__device__ __nv_bfloat16 g_xs_h[3][(size_t)NTOK * D_];
__device__ __nv_bfloat16 g_xs_l[3][(size_t)NTOK * D_];
__device__ __nv_bfloat16 g_ws_h[4][(size_t)D_ * D_];
__device__ __nv_bfloat16 g_ws_l[4][(size_t)D_ * D_];
__device__ __nv_bfloat16 g_hd_h[3][(size_t)NTOK * D_];   // head-split q/k/v
__device__ __nv_bfloat16 g_hd_l[3][(size_t)NTOK * D_];
__device__ __nv_bfloat16 g_cat_h[(size_t)NTOK * D_];
__device__ __nv_bfloat16 g_cat_l[(size_t)NTOK * D_];

// ---------------- helpers -----------------------------------------------------
__device__ __forceinline__ uint32_t smem_u32(const void* p) {
    uint32_t a;
    asm("{ .reg .u64 t; cvta.to.shared.u64 t, %1; cvt.u32.u64 %0, t; }" : "=r"(a) : "l"(p));
    return a;
}
__device__ __forceinline__ void mma_bf16(float c[4], const uint32_t a[4],
                                         uint32_t b0, uint32_t b1) {
    asm volatile("mma.sync.aligned.m16n8k16.row.col.f32.bf16.bf16.f32 "
        "{%0,%1,%2,%3}, {%4,%5,%6,%7}, {%8,%9}, {%0,%1,%2,%3};"
        : "+f"(c[0]), "+f"(c[1]), "+f"(c[2]), "+f"(c[3])
        : "r"(a[0]), "r"(a[1]), "r"(a[2]), "r"(a[3]), "r"(b0), "r"(b1));
}
__device__ __forceinline__ void ldsm4(uint32_t r[4], uint32_t a) {
    asm volatile("ldmatrix.sync.aligned.m8n8.x4.shared.b16 {%0,%1,%2,%3}, [%4];"
        : "=r"(r[0]), "=r"(r[1]), "=r"(r[2]), "=r"(r[3]) : "r"(a));
}
__device__ __forceinline__ void ldsm4t(uint32_t r[4], uint32_t a) {
    asm volatile("ldmatrix.sync.aligned.m8n8.x4.trans.shared.b16 {%0,%1,%2,%3}, [%4];"
        : "=r"(r[0]), "=r"(r[1]), "=r"(r[2]), "=r"(r[3]) : "r"(a));
}
__device__ __forceinline__ void split2(float x, float y, uint32_t& hi, uint32_t& lo) {
    __nv_bfloat16 hx = __float2bfloat16(x), hy = __float2bfloat16(y);
    __nv_bfloat16 lx = __float2bfloat16(x - __bfloat162float(hx));
    __nv_bfloat16 ly = __float2bfloat16(y - __bfloat162float(hy));
    __nv_bfloat162 h(hx, hy), l(lx, ly);
    hi = *(uint32_t*)&h;
    lo = *(uint32_t*)&l;
}
__device__ __forceinline__ void cp16(uint32_t smem, const void* g) {
    asm volatile("cp.async.cg.shared.global [%0], [%1], 16;" :: "r"(smem), "l"(g));
}
#define CP_COMMIT() asm volatile("cp.async.commit_group;" ::: "memory")
template<int N> __device__ __forceinline__ void cp_wait() {
    asm volatile("cp.async.wait_group %0;" :: "n"(N) : "memory");
}

// ---------------- prep: split inputs + weights --------------------------------
__global__ void __launch_bounds__(256) split_all(
    const float* __restrict__ q, const float* __restrict__ k, const float* __restrict__ v,
    const float* __restrict__ wq, const float* __restrict__ wk,
    const float* __restrict__ wv, const float* __restrict__ wc)
{
    int i = blockIdx.x * 256 + threadIdx.x;          // float4 index
    const float* src;
    __nv_bfloat16 *dh, *dl;
    int off;
    if (i < 3 * 1048576) {
        int ti = i >> 20; off = i & 1048575;
        src = (ti == 0) ? q : (ti == 1) ? k : v;
        dh = g_xs_h[ti]; dl = g_xs_l[ti];
    } else {
        int j = i - 3145728;
        int ti = j >> 18; off = j & 262143;
        src = (ti == 0) ? wq : (ti == 1) ? wk : (ti == 2) ? wv : wc;
        dh = g_ws_h[ti]; dl = g_ws_l[ti];
    }
    float4 x = ((const float4*)src)[off];
    uint32_t h01, l01, h23, l23;
    split2(x.x, x.y, h01, l01);
    split2(x.z, x.w, h23, l23);
    ((uint2*)dh)[off] = make_uint2(h01, h23);
    ((uint2*)dl)[off] = make_uint2(l01, l23);
}

// ---------------- projection GEMM (R5 config: chunk 64, 3-stage, 1 CTA/SM) ----
__global__ void __launch_bounds__(256, 1)
proj_tc(const float* __restrict__ bq, const float* __restrict__ bk,
        const float* __restrict__ bv, const float* __restrict__ bc,
        float* __restrict__ Yout, int mode_base)
{
    extern __shared__ __align__(1024) char smp[];
    uint32_t sb = smem_u32(smp);
    const int t = threadIdx.x, lane = t & 31, wid = t >> 5;
    const int wy = wid >> 2, wx = wid & 3;
    const int mode = mode_base + blockIdx.z;
    const __nv_bfloat16 *Xh, *Xl;
    if (mode < 3) { Xh = g_xs_h[mode]; Xl = g_xs_l[mode]; }
    else          { Xh = g_cat_h;      Xl = g_cat_l; }
    const __nv_bfloat16 *Wh = g_ws_h[mode], *Wl = g_ws_l[mode];
    const float* bias = (mode == 0) ? bq : (mode == 1) ? bk : (mode == 2) ? bv : bc;
    const int bm = blockIdx.y * 128, bn = blockIdx.x * 128;

    float acc[4][4][4];
#pragma unroll
    for (int i = 0; i < 4; i++)
#pragma unroll
        for (int j = 0; j < 4; j++)
#pragma unroll
            for (int k = 0; k < 4; k++) acc[i][j][k] = 0.0f;

#define PJ_PF(c) do { \
    const int kc_ = (c) * 64; \
    uint32_t bo_ = sb + ((c) % 3) * 65536; \
    _Pragma("unroll") \
    for (int i_ = 0; i_ < 4; i_++) { \
        int e_ = i_ * 256 + t, r_ = e_ >> 3, c8_ = e_ & 7; \
        uint32_t so_ = r_ * 128 + ((c8_ ^ (r_ & 7)) << 4); \
        const size_t g_ = (size_t)(bm + r_) * D_ + kc_ + c8_ * 8; \
        cp16(bo_ + so_,         Xh + g_); \
        cp16(bo_ + 16384 + so_, Xl + g_); \
    } \
    _Pragma("unroll") \
    for (int i_ = 0; i_ < 4; i_++) { \
        int e_ = i_ * 256 + t, k_ = e_ >> 4, b_ = e_ & 15; \
        uint32_t so_ = k_ * 256 + ((b_ ^ (k_ & 7)) << 4); \
        const size_t g_ = (size_t)(kc_ + k_) * D_ + bn + b_ * 8; \
        cp16(bo_ + 32768 + so_, Wh + g_); \
        cp16(bo_ + 49152 + so_, Wl + g_); \
    } \
    CP_COMMIT(); \
} while (0)

#define PJ_MMA(base) do { \
    uint32_t aAH = (base), aAL = (base) + 16384, aBH = (base) + 32768, aBL = (base) + 49152; \
    _Pragma("unroll") \
    for (int s = 0; s < 4; s++) { \
        const int rA0 = wy * 64 + ((lane >> 3) & 1) * 8 + (lane & 7); \
        const int cA = 2 * s + (lane >> 4); \
        uint32_t ah[4][4], al[4][4]; \
        _Pragma("unroll") \
        for (int mi = 0; mi < 4; mi++) { \
            int r = rA0 + mi * 16; \
            uint32_t off = r * 128 + ((cA ^ (r & 7)) << 4); \
            ldsm4(ah[mi], aAH + off); \
            ldsm4(al[mi], aAL + off); \
        } \
        const int rB = 16 * s + ((lane >> 3) & 1) * 8 + (lane & 7); \
        uint32_t bh[2][4], bl[2][4]; \
        _Pragma("unroll") \
        for (int nh = 0; nh < 2; nh++) { \
            int cB = ((wx * 32 + nh * 16) >> 3) + ((lane >> 4) & 1); \
            uint32_t off = rB * 256 + ((cB ^ (rB & 7)) << 4); \
            ldsm4t(bh[nh], aBH + off); \
            ldsm4t(bl[nh], aBL + off); \
        } \
        _Pragma("unroll") \
        for (int mi = 0; mi < 4; mi++) \
            _Pragma("unroll") \
            for (int nj = 0; nj < 4; nj++) { \
                uint32_t bh0 = bh[nj >> 1][(nj & 1) * 2], bh1 = bh[nj >> 1][(nj & 1) * 2 + 1]; \
                uint32_t bl0 = bl[nj >> 1][(nj & 1) * 2], bl1 = bl[nj >> 1][(nj & 1) * 2 + 1]; \
                mma_bf16(acc[mi][nj], ah[mi], bh0, bh1); \
                mma_bf16(acc[mi][nj], ah[mi], bl0, bl1); \
                mma_bf16(acc[mi][nj], al[mi], bh0, bh1); \
            } \
    } \
} while (0)

    PJ_PF(0); PJ_PF(1);
#pragma unroll 1
    for (int c = 0; c < 16; c++) {
        if (c + 2 < 16) PJ_PF(c + 2);
        if (c < 14) cp_wait<2>(); else if (c == 14) cp_wait<1>(); else cp_wait<0>();
        __syncthreads();
        PJ_MMA(sb + (c % 3) * 65536);
        __syncthreads();
    }

    const int er = lane >> 2, ec = (lane & 3) * 2;
    if (mode < 3) {
        __nv_bfloat16* dh = g_hd_h[mode];
        __nv_bfloat16* dl = g_hd_l[mode];
#pragma unroll
        for (int mi = 0; mi < 4; mi++)
#pragma unroll
            for (int nj = 0; nj < 4; nj++) {
                const int col = bn + wx * 32 + nj * 8 + ec;
                const float b0 = __ldg(bias + col), b1 = __ldg(bias + col + 1);
                const int row0 = bm + wy * 64 + mi * 16 + er;
#pragma unroll
                for (int h = 0; h < 2; h++) {
                    const int row = row0 + h * 8;
                    uint32_t hv, lv;
                    split2(acc[mi][nj][h * 2] + b0, acc[mi][nj][h * 2 + 1] + b1, hv, lv);
                    int bb = row >> 11, ss = row & (S_ - 1), hh = col >> 6, dd = col & (DH_ - 1);
                    size_t idx = (((size_t)(bb * H_ + hh)) * S_ + ss) * DH_ + dd;
                    *(uint32_t*)(dh + idx) = hv;
                    *(uint32_t*)(dl + idx) = lv;
                }
            }
    } else {
#pragma unroll
        for (int mi = 0; mi < 4; mi++)
#pragma unroll
            for (int nj = 0; nj < 4; nj++) {
                const int col = bn + wx * 32 + nj * 8 + ec;
                const float b0 = __ldg(bias + col), b1 = __ldg(bias + col + 1);
                const int row0 = bm + wy * 64 + mi * 16 + er;
#pragma unroll
                for (int h = 0; h < 2; h++) {
                    float2 v = make_float2(acc[mi][nj][h * 2] + b0, acc[mi][nj][h * 2 + 1] + b1);
                    *(float2*)(Yout + (size_t)(row0 + h * 8) * D_ + col) = v;
                }
            }
    }
}

// ---------------- fused attention (flash-style recompute) ---------------------
// SMEM (96KB dynamic):
//  Q:     QH @0 (16K), QL @16K                                    [persistent]
//  pass1: K tiles 128 rows: buf0 @32K (hi16K lo16K), buf1 @64K
//  pass2: K2 @32K (hi8K @32K, lo8K @40K), V2 @48K (hi8K, lo8K @56K),
//         P @64K (hi16K @64K, lo16K @80K)
__global__ void __launch_bounds__(256, 2) fused_attn(float* __restrict__ attn)
{
    extern __shared__ __align__(1024) char smp[];
    __shared__ float2 s_red[128][4];
    __shared__ float sm_m[128], sm_s[128], sm_i[128];
    uint32_t sb = smem_u32(smp);
    const int t = threadIdx.x, lane = t & 31, wid = t >> 5;
    const int bh = blockIdx.y, q0 = blockIdx.x * 128;
    const __nv_bfloat16* Qh = g_hd_h[0] + (size_t)bh * S_ * DH_;
    const __nv_bfloat16* Ql = g_hd_l[0] + (size_t)bh * S_ * DH_;
    const __nv_bfloat16* Kh = g_hd_h[1] + (size_t)bh * S_ * DH_;
    const __nv_bfloat16* Kl = g_hd_l[1] + (size_t)bh * S_ * DH_;
    const __nv_bfloat16* Vh = g_hd_h[2] + (size_t)bh * S_ * DH_;
    const __nv_bfloat16* Vl = g_hd_l[2] + (size_t)bh * S_ * DH_;
    float* A = attn + (size_t)bh * S_ * S_;

    if (t < 128) { sm_m[t] = -1e30f; sm_s[t] = 0.0f; }

    // ---- load Q (grouped with K0) ----
#pragma unroll
    for (int i = 0; i < 4; i++) {
        int e = i * 256 + t, r = e >> 3, c8 = e & 7;
        uint32_t so = r * 128 + ((c8 ^ (r & 7)) << 4);
        cp16(sb + so,         Qh + (size_t)(q0 + r) * DH_ + c8 * 8);
        cp16(sb + 16384 + so, Ql + (size_t)(q0 + r) * DH_ + c8 * 8);
    }
#define FA_KPF(kt) do { \
    uint32_t kb_ = sb + 32768 + ((kt) & 1) * 32768; \
    _Pragma("unroll") \
    for (int i_ = 0; i_ < 4; i_++) { \
        int e_ = i_ * 256 + t, r_ = e_ >> 3, c8_ = e_ & 7; \
        uint32_t so_ = r_ * 128 + ((c8_ ^ (r_ & 7)) << 4); \
        cp16(kb_ + so_,         Kh + (size_t)((kt) * 128 + r_) * DH_ + c8_ * 8); \
        cp16(kb_ + 16384 + so_, Kl + (size_t)((kt) * 128 + r_) * DH_ + c8_ * 8); \
    } \
    CP_COMMIT(); \
} while (0)

    FA_KPF(0);
    FA_KPF(1);

    // ========== PASS 1: online softmax stats (no S write) ==========
    {
        const int wy = wid >> 2, wx = wid & 3;       // warp 64q x 32k
        const int er = lane >> 2;
#pragma unroll 1
        for (int kt = 0; kt < 16; kt++) {
            if (kt == 15) cp_wait<0>(); else cp_wait<1>();
            __syncthreads();

            float acc[4][4][4];
#pragma unroll
            for (int i = 0; i < 4; i++)
#pragma unroll
                for (int j = 0; j < 4; j++)
#pragma unroll
                    for (int k = 0; k < 4; k++) acc[i][j][k] = 0.0f;

            const uint32_t aQH = sb, aQL = sb + 16384;
            const uint32_t aKH = sb + 32768 + (kt & 1) * 32768, aKL = aKH + 16384;
#pragma unroll
            for (int s = 0; s < 4; s++) {
                const int rA0 = wy * 64 + ((lane >> 3) & 1) * 8 + (lane & 7);
                const int cA = 2 * s + (lane >> 4);
                uint32_t ah[4][4], al[4][4];
#pragma unroll
                for (int mi = 0; mi < 4; mi++) {
                    int r = rA0 + mi * 16;
                    uint32_t off = r * 128 + ((cA ^ (r & 7)) << 4);
                    ldsm4(ah[mi], aQH + off);
                    ldsm4(al[mi], aQL + off);
                }
                uint32_t bhf[2][4], blf[2][4];
                const int cB = 2 * s + ((lane >> 3) & 1);
#pragma unroll
                for (int nh = 0; nh < 2; nh++) {
                    int r = wx * 32 + nh * 16 + ((lane >> 4) & 1) * 8 + (lane & 7);
                    uint32_t off = r * 128 + ((cB ^ (r & 7)) << 4);
                    ldsm4(bhf[nh], aKH + off);
                    ldsm4(blf[nh], aKL + off);
                }
#pragma unroll
                for (int mi = 0; mi < 4; mi++)
#pragma unroll
                    for (int nj = 0; nj < 4; nj++) {
                        uint32_t b0 = bhf[nj >> 1][(nj & 1) * 2], b1 = bhf[nj >> 1][(nj & 1) * 2 + 1];
                        uint32_t c0 = blf[nj >> 1][(nj & 1) * 2], c1 = blf[nj >> 1][(nj & 1) * 2 + 1];
                        mma_bf16(acc[mi][nj], ah[mi], b0, b1);
                        mma_bf16(acc[mi][nj], ah[mi], c0, c1);
                        mma_bf16(acc[mi][nj], al[mi], b0, b1);
                    }
            }

            // warp-local (max, sumexp) partials on scaled logits
#pragma unroll
            for (int mi = 0; mi < 4; mi++)
#pragma unroll
                for (int h = 0; h < 2; h++) {
                    float m = -1e30f;
#pragma unroll
                    for (int nj = 0; nj < 4; nj++)
                        m = fmaxf(m, fmaxf(acc[mi][nj][h * 2], acc[mi][nj][h * 2 + 1]));
                    m *= 0.125f;
                    float s = 0.0f;
#pragma unroll
                    for (int nj = 0; nj < 4; nj++)
                        s += __expf(acc[mi][nj][h * 2] * 0.125f - m)
                           + __expf(acc[mi][nj][h * 2 + 1] * 0.125f - m);
                    // merge across the 4-lane group (cols)
                    float m2 = fmaxf(m, __shfl_xor_sync(0xffffffffu, m, 1));
                    float s2 = s * __expf(m - m2) + __shfl_xor_sync(0xffffffffu, s, 1) *
                               __expf(__shfl_xor_sync(0xffffffffu, m, 1) - m2);
                    float m3 = fmaxf(m2, __shfl_xor_sync(0xffffffffu, m2, 2));
                    float s3 = s2 * __expf(m2 - m3) + __shfl_xor_sync(0xffffffffu, s2, 2) *
                               __expf(__shfl_xor_sync(0xffffffffu, m2, 2) - m3);
                    if ((lane & 3) == 0)
                        s_red[wy * 64 + mi * 16 + h * 8 + er][wx] = make_float2(m3, s3);
                }
            __syncthreads();
            if (t < 128) {
                float2 p0 = s_red[t][0], p1 = s_red[t][1], p2 = s_red[t][2], p3 = s_red[t][3];
                float mt = fmaxf(fmaxf(p0.x, p1.x), fmaxf(p2.x, p3.x));
                float st = p0.y * __expf(p0.x - mt) + p1.y * __expf(p1.x - mt)
                         + p2.y * __expf(p2.x - mt) + p3.y * __expf(p3.x - mt);
                float mo = sm_m[t];
                float mn = fmaxf(mo, mt);
                sm_s[t] = sm_s[t] * __expf(mo - mn) + st * __expf(mt - mn);
                sm_m[t] = mn;
            }
            if (kt + 2 < 16) FA_KPF(kt + 2);
        }
    }
    __syncthreads();
    if (t < 128) sm_i[t] = 1.0f / sm_s[t];
    __syncthreads();

    // ========== PASS 2: recompute S, write p, O = p @ V ==========
    {
        const uint32_t aQH = sb, aQL = sb + 16384;
        const uint32_t K2H = sb + 32768, K2L = sb + 40960;
        const uint32_t V2H = sb + 49152, V2L = sb + 57344;
        const uint32_t PH  = sb + 65536, PL  = sb + 81920;
        const int wy2 = wid >> 2, wx2 = wid & 3;   // S: warp 64q x 16k
        const int wy3 = wid >> 1, wx3 = wid & 1;   // O: warp 32q x 32d
        const int er = lane >> 2, ec = (lane & 3) * 2;

#define KPF2(c) do { \
    const int kc_ = (c) * 64; \
    _Pragma("unroll") \
    for (int i_ = 0; i_ < 2; i_++) { \
        int e_ = i_ * 256 + t, r_ = e_ >> 3, c8_ = e_ & 7; \
        uint32_t so_ = r_ * 128 + ((c8_ ^ (r_ & 7)) << 4); \
        cp16(K2H + so_, Kh + (size_t)(kc_ + r_) * DH_ + c8_ * 8); \
        cp16(K2L + so_, Kl + (size_t)(kc_ + r_) * DH_ + c8_ * 8); \
    } \
    CP_COMMIT(); \
} while (0)
#define VPF2(c) do { \
    const int kc_ = (c) * 64; \
    _Pragma("unroll") \
    for (int i_ = 0; i_ < 2; i_++) { \
        int e_ = i_ * 256 + t, r_ = e_ >> 3, c8_ = e_ & 7; \
        uint32_t so_ = r_ * 128 + ((c8_ ^ (r_ & 7)) << 4); \
        cp16(V2H + so_, Vh + (size_t)(kc_ + r_) * DH_ + c8_ * 8); \
        cp16(V2L + so_, Vl + (size_t)(kc_ + r_) * DH_ + c8_ * 8); \
    } \
    CP_COMMIT(); \
} while (0)

        float accO[2][4][4];
#pragma unroll
        for (int i = 0; i < 2; i++)
#pragma unroll
            for (int j = 0; j < 4; j++)
#pragma unroll
                for (int k = 0; k < 4; k++) accO[i][j][k] = 0.0f;

        KPF2(0);
        VPF2(0);
#pragma unroll 1
        for (int c = 0; c < 32; c++) {
            cp_wait<0>();
            __syncthreads();

            // MMA1: S chunk = Q(128x64) x K_c^T(64x64)  -> warp 64q x 16k
            float accS[4][2][4];
#pragma unroll
            for (int i = 0; i < 4; i++)
#pragma unroll
                for (int j = 0; j < 2; j++)
#pragma unroll
                    for (int k = 0; k < 4; k++) accS[i][j][k] = 0.0f;
#pragma unroll
            for (int s = 0; s < 4; s++) {
                const int rA0 = wy2 * 64 + ((lane >> 3) & 1) * 8 + (lane & 7);
                const int cA = 2 * s + (lane >> 4);
                uint32_t ah[4][4], al[4][4];
#pragma unroll
                for (int mi = 0; mi < 4; mi++) {
                    int r = rA0 + mi * 16;
                    uint32_t off = r * 128 + ((cA ^ (r & 7)) << 4);
                    ldsm4(ah[mi], aQH + off);
                    ldsm4(al[mi], aQL + off);
                }
                const int rK = wx2 * 16 + ((lane >> 4) & 1) * 8 + (lane & 7);
                const int cB = 2 * s + ((lane >> 3) & 1);
                uint32_t bhf[4], blf[4];
                {
                    uint32_t off = rK * 128 + ((cB ^ (rK & 7)) << 4);
                    ldsm4(bhf, K2H + off);
                    ldsm4(blf, K2L + off);
                }
#pragma unroll
                for (int mi = 0; mi < 4; mi++)
#pragma unroll
                    for (int nj = 0; nj < 2; nj++) {
                        uint32_t b0 = bhf[nj * 2], b1 = bhf[nj * 2 + 1];
                        uint32_t c0 = blf[nj * 2], c1 = blf[nj * 2 + 1];
                        mma_bf16(accS[mi][nj], ah[mi], b0, b1);
                        mma_bf16(accS[mi][nj], ah[mi], c0, c1);
                        mma_bf16(accS[mi][nj], al[mi], b0, b1);
                    }
            }
            __syncthreads();           // K2 free (all warps done with ldsm)
            if (c + 1 < 32) KPF2(c + 1);

            // p-transform: write p to gmem + stage split p in SMEM
            const int kc = c * 64;
#pragma unroll
            for (int mi = 0; mi < 4; mi++)
#pragma unroll
                for (int nj = 0; nj < 2; nj++)
#pragma unroll
                    for (int h = 0; h < 2; h++) {
                        const int rl = wy2 * 64 + mi * 16 + h * 8 + er;
                        const float m_ = sm_m[rl], i_ = sm_i[rl];
                        float p0 = __expf(accS[mi][nj][h * 2]     * 0.125f - m_) * i_;
                        float p1 = __expf(accS[mi][nj][h * 2 + 1] * 0.125f - m_) * i_;
                        const int col = wx2 * 16 + nj * 8 + ec;
                        *(float2*)(A + (size_t)(q0 + rl) * S_ + kc + col) = make_float2(p0, p1);
                        uint32_t hv, lv;
                        split2(p0, p1, hv, lv);
                        uint32_t offP = rl * 128 + ((((wx2 * 2 + nj) ^ (rl & 7)) << 4)) + (lane & 3) * 4;
                        *(uint32_t*)(PH + 0 + offP - sb + (size_t)smp) = hv;   // placeholder
                        *(uint32_t*)(PL + 0 + offP - sb + (size_t)smp) = lv;
                    }
            __syncthreads();           // P visible

            // MMA2: O += P(128x64) x V_c(64x64)  -> warp 32q x 32d
#pragma unroll
            for (int s = 0; s < 4; s++) {
                const int rA0 = wy3 * 32 + ((lane >> 3) & 1) * 8 + (lane & 7);
                const int cA = 2 * s + (lane >> 4);
                uint32_t ah[2][4], al[2][4];
#pragma unroll
                for (int mi = 0; mi < 2; mi++) {
                    int r = rA0 + mi * 16;
                    uint32_t off = r * 128 + ((cA ^ (r & 7)) << 4);
                    ldsm4(ah[mi], PH + off);
                    ldsm4(al[mi], PL + off);
                }
                const int rB = 16 * s + ((lane >> 3) & 1) * 8 + (lane & 7);
                uint32_t bh2[2][4], bl2[2][4];
#pragma unroll
                for (int nh = 0; nh < 2; nh++) {
                    int cB = ((wx3 * 32 + nh * 16) >> 3) + ((lane >> 4) & 1);
                    uint32_t off = rB * 128 + ((cB ^ (rB & 7)) << 4);
                    ldsm4t(bh2[nh], V2H + off);
                    ldsm4t(bl2[nh], V2L + off);
                }
#pragma unroll
                for (int mi = 0; mi < 2; mi++)
#pragma unroll
                    for (int nj = 0; nj < 4; nj++) {
                        uint32_t b0 = bh2[nj >> 1][(nj & 1) * 2], b1 = bh2[nj >> 1][(nj & 1) * 2 + 1];
                        uint32_t c0 = bl2[nj >> 1][(nj & 1) * 2], c1 = bl2[nj >> 1][(nj & 1) * 2 + 1];
                        mma_bf16(accO[mi][nj], ah[mi], b0, b1);
                        mma_bf16(accO[mi][nj], ah[mi], c0, c1);
                        mma_bf16(accO[mi][nj], al[mi], b0, b1);
                    }
            }
            __syncthreads();           // V2 free
            if (c + 1 < 32) VPF2(c + 1);
        }

        // epilogue: O -> g_cat (split)
        const int bb = bh >> 4, hh = bh & (H_ - 1);
#pragma unroll
        for (int mi = 0; mi < 2; mi++)
#pragma unroll
            for (int nj = 0; nj < 4; nj++) {
                const int dd = wx3 * 32 + nj * 8 + ec;
                const int row0 = q0 + wy3 * 32 + mi * 16 + er;
#pragma unroll
                for (int h = 0; h < 2; h++) {
                    const int ss = row0 + h * 8;
                    uint32_t hv, lv;
                    split2(accO[mi][nj][h * 2], accO[mi][nj][h * 2 + 1], hv, lv);
                    size_t idx = ((size_t)(bb * S_ + ss)) * D_ + hh * DH_ + dd;
                    *(uint32_t*)(g_cat_h + idx) = hv;
                    *(uint32_t*)(g_cat_l + idx) = lv;
                }
            }
    }
}

// ---------------- launch ------------------------------------------------------
extern "C" void kernel_launch(void* const* d_in, const int* in_sizes, int n_in,
                              void* d_out, int out_size)
{
    const float* q  = (const float*)d_in[0];
    const float* k  = (const float*)d_in[1];
    const float* v  = (const float*)d_in[2];
    const float* Wq = (const float*)d_in[3];
    const float* bq = (const float*)d_in[4];
    const float* Wk = (const float*)d_in[5];
    const float* bk = (const float*)d_in[6];
    const float* Wv = (const float*)d_in[7];
    const float* bv = (const float*)d_in[8];
    const float* Wc = (const float*)d_in[9];
    const float* bc = (const float*)d_in[10];

    float* out  = (float*)d_out;
    float* attn = out + OUT_ELEMS;

    const int SM_PROJ = 196608;
    const int SM_FA   = 98304;
    cudaFuncSetAttribute(proj_tc,    cudaFuncAttributeMaxDynamicSharedMemorySize, SM_PROJ);
    cudaFuncSetAttribute(fused_attn, cudaFuncAttributeMaxDynamicSharedMemorySize, SM_FA);

    split_all<<<16384, 256>>>(q, k, v, Wq, Wk, Wv, Wc);

    proj_tc<<<dim3(8, 32, 3), 256, SM_PROJ>>>(bq, bk, bv, bc, nullptr, 0);

    fused_attn<<<dim3(16, 32), 256, SM_FA>>>(attn);

    proj_tc<<<dim3(8, 32, 1), 256, SM_PROJ>>>(bq, bk, bv, bc, out, 3);
}